// round 3
// baseline (speedup 1.0000x reference)
#include <cuda_runtime.h>

#define B_TOT 4096
#define N_DIM 64
#define H_DIM 256
#define GB    8                 // batch rows per block in fused kernel
#define NBLK  (B_TOT / GB)      // 512

// Precomputed A[n,k] = sum_h h[n,h]*U_w[k,h] + w[n,h]*V_w[k,h]
__device__ float g_A[N_DIM * H_DIM];

// ---------------------------------------------------------------------------
// Kernel A: precompute A[n,k].  grid = 64 (one per n), 256 threads (one per k)
// U/V staged through padded smem tiles for coalesced global access.
// ---------------------------------------------------------------------------
__global__ __launch_bounds__(256) void precompute_A_kernel(
    const float* __restrict__ h_in, const float* __restrict__ w_in,
    const float* __restrict__ U_w, const float* __restrict__ V_w)
{
    __shared__ float hrow[H_DIM];
    __shared__ float wrow[H_DIM];
    __shared__ float utile[H_DIM * 20];   // 16 floats + 4 pad per row
    __shared__ float vtile[H_DIM * 20];

    const int n = blockIdx.x;
    const int t = threadIdx.x;

    hrow[t] = h_in[n * H_DIM + t];
    wrow[t] = w_in[n * H_DIM + t];

    const float4* U4  = (const float4*)U_w;
    const float4* V4  = (const float4*)V_w;
    float4*       ut4 = (float4*)utile;
    float4*       vt4 = (float4*)vtile;
    const float4* hr4 = (const float4*)hrow;
    const float4* wr4 = (const float4*)wrow;

    float acc = 0.0f;

    #pragma unroll 1
    for (int c = 0; c < 16; c++) {
        __syncthreads();
        #pragma unroll
        for (int it = 0; it < 4; it++) {
            int idx = it * 256 + t;
            int kk  = idx >> 2;
            int j   = idx & 3;
            ut4[kk * 5 + j] = U4[kk * 64 + c * 4 + j];
            vt4[kk * 5 + j] = V4[kk * 64 + c * 4 + j];
        }
        __syncthreads();
        #pragma unroll
        for (int j = 0; j < 4; j++) {
            float4 u  = ut4[t * 5 + j];
            float4 v  = vt4[t * 5 + j];
            float4 hh = hr4[c * 4 + j];
            float4 ww = wr4[c * 4 + j];
            acc = fmaf(u.x, hh.x, acc); acc = fmaf(u.y, hh.y, acc);
            acc = fmaf(u.z, hh.z, acc); acc = fmaf(u.w, hh.w, acc);
            acc = fmaf(v.x, ww.x, acc); acc = fmaf(v.y, ww.y, acc);
            acc = fmaf(v.z, ww.z, acc); acc = fmaf(v.w, ww.w, acc);
        }
    }
    g_A[n * H_DIM + t] = acc;
}

// ---------------------------------------------------------------------------
// Kernel B: fused gate + Ws GEMM + candidate + normalize.
// grid = 512 blocks, each handles 8 batch rows; 256 threads = 8 warps.
// warp wid owns n = wid*8..wid*8+7; lane owns k in {4l..4l+3, 128+4l..128+4l+3}
// ---------------------------------------------------------------------------
__global__ __launch_bounds__(256) void fused_update_kernel(
    const float* __restrict__ s_t, const float* __restrict__ h_in,
    const float* __restrict__ w_in, const float* __restrict__ W_w,
    const float* __restrict__ prelu_a, float* __restrict__ out)
{
    __shared__ float ssm [GB * H_DIM];    // s_t rows          8 KB
    __shared__ float wssm[GB * H_DIM];    // Ws[b][k]          8 KB
    __shared__ float gsm [GB * N_DIM];    // gate[b][n]        2 KB
    __shared__ float wtile[H_DIM * 20];   // W chunk (padded) 20 KB

    const int t    = threadIdx.x;
    const int lane = t & 31;
    const int wid  = t >> 5;
    const int b0   = blockIdx.x * GB;

    // ---- Phase 0: load s rows into smem (coalesced) ----
    #pragma unroll
    for (int p = 0; p < GB; p++)
        ssm[p * H_DIM + t] = s_t[(b0 + p) * H_DIM + t];

    // ---- Phase 1: Ws[g][k] = sum_h s[g][h] * W_w[k][h], thread t owns k=t ----
    const float4* W4   = (const float4*)W_w;
    float4*       wt4  = (float4*)wtile;
    const float4* ssm4 = (const float4*)ssm;

    float wacc[GB];
    #pragma unroll
    for (int g = 0; g < GB; g++) wacc[g] = 0.0f;

    #pragma unroll 1
    for (int c = 0; c < 16; c++) {
        __syncthreads();
        #pragma unroll
        for (int it = 0; it < 4; it++) {
            int idx = it * 256 + t;
            int kk  = idx >> 2;
            int j   = idx & 3;
            wt4[kk * 5 + j] = W4[kk * 64 + c * 4 + j];
        }
        __syncthreads();
        #pragma unroll
        for (int j = 0; j < 4; j++) {
            float4 wv = wt4[t * 5 + j];
            #pragma unroll
            for (int g = 0; g < GB; g++) {
                float4 sv = ssm4[g * 64 + c * 4 + j];  // broadcast
                float a = wacc[g];
                a = fmaf(wv.x, sv.x, a); a = fmaf(wv.y, sv.y, a);
                a = fmaf(wv.z, sv.z, a); a = fmaf(wv.w, sv.w, a);
                wacc[g] = a;
            }
        }
    }
    #pragma unroll
    for (int g = 0; g < GB; g++) wssm[g * H_DIM + t] = wacc[g];

    // ---- Phase 2: gate[g][n] = sigmoid( sum_h (h+w)[n,h] * s[g,h] ) ----
    const float4* h4 = (const float4*)h_in;
    const float4* w4 = (const float4*)w_in;

    #pragma unroll 1
    for (int i = 0; i < 8; i++) {
        int n = wid * 8 + i;
        float4 ha = h4[n * 64 + lane];
        float4 hb = h4[n * 64 + 32 + lane];
        float4 wa = w4[n * 64 + lane];
        float4 wb = w4[n * 64 + 32 + lane];
        float4 xa = make_float4(ha.x + wa.x, ha.y + wa.y, ha.z + wa.z, ha.w + wa.w);
        float4 xb = make_float4(hb.x + wb.x, hb.y + wb.y, hb.z + wb.z, hb.w + wb.w);

        float acc[GB];
        #pragma unroll
        for (int g = 0; g < GB; g++) {
            float4 sa = ssm4[g * 64 + lane];
            float4 sb = ssm4[g * 64 + 32 + lane];
            float a = 0.0f;
            a = fmaf(xa.x, sa.x, a); a = fmaf(xa.y, sa.y, a);
            a = fmaf(xa.z, sa.z, a); a = fmaf(xa.w, sa.w, a);
            a = fmaf(xb.x, sb.x, a); a = fmaf(xb.y, sb.y, a);
            a = fmaf(xb.z, sb.z, a); a = fmaf(xb.w, sb.w, a);
            acc[g] = a;
        }
        #pragma unroll
        for (int g = 0; g < GB; g++) {
            #pragma unroll
            for (int off = 16; off > 0; off >>= 1)
                acc[g] += __shfl_xor_sync(0xffffffffu, acc[g], off);
        }
        if (lane == 0) {
            #pragma unroll
            for (int g = 0; g < GB; g++)
                gsm[g * N_DIM + n] = 1.0f / (1.0f + __expf(-acc[g]));
        }
    }
    __syncthreads();   // gsm + wssm visible to all

    // ---- Phase 3: candidate + normalize + store ----
    const float  a0   = prelu_a[0];
    const float4* A4  = (const float4*)g_A;
    const float4* ws4 = (const float4*)wssm;
    float4*       o4  = (float4*)out;

    #pragma unroll 1
    for (int i = 0; i < 8; i++) {
        int n = wid * 8 + i;
        float4 Aa = A4[n * 64 + lane];
        float4 Ab = A4[n * 64 + 32 + lane];
        float4 ha = h4[n * 64 + lane];
        float4 hb = h4[n * 64 + 32 + lane];

        #pragma unroll
        for (int g = 0; g < GB; g++) {
            float4 wa = ws4[g * 64 + lane];
            float4 wb = ws4[g * 64 + 32 + lane];
            float  gv = gsm[g * N_DIM + n];

            float v0, v1, v2, v3, v4v, v5, v6, v7;
            float ss = 0.0f;
            #define COMP(vv, Ae, we, he)                                     \
                {                                                            \
                    float x = (Ae) + (we);                                   \
                    float c = fmaxf(x, 0.0f) + a0 * fminf(x, 0.0f);          \
                    vv = fmaf(gv, c, (he));                                  \
                    ss = fmaf(vv, vv, ss);                                   \
                }
            COMP(v0,  Aa.x, wa.x, ha.x)
            COMP(v1,  Aa.y, wa.y, ha.y)
            COMP(v2,  Aa.z, wa.z, ha.z)
            COMP(v3,  Aa.w, wa.w, ha.w)
            COMP(v4v, Ab.x, wb.x, hb.x)
            COMP(v5,  Ab.y, wb.y, hb.y)
            COMP(v6,  Ab.z, wb.z, hb.z)
            COMP(v7,  Ab.w, wb.w, hb.w)
            #undef COMP

            #pragma unroll
            for (int off = 16; off > 0; off >>= 1)
                ss += __shfl_xor_sync(0xffffffffu, ss, off);
            float inv = rsqrtf(ss);

            long base = ((long)(b0 + g) * N_DIM + n) * 64;
            o4[base + lane]      = make_float4(v0 * inv, v1 * inv, v2 * inv, v3 * inv);
            o4[base + 32 + lane] = make_float4(v4v * inv, v5 * inv, v6 * inv, v7 * inv);
        }
    }
}

// ---------------------------------------------------------------------------
extern "C" void kernel_launch(void* const* d_in, const int* in_sizes, int n_in,
                              void* d_out, int out_size)
{
    const float* s_t     = (const float*)d_in[0];   // [4096,256]
    const float* h_in    = (const float*)d_in[1];   // [1,64,256]
    const float* w_in    = (const float*)d_in[2];   // [1,64,256]
    const float* U_w     = (const float*)d_in[3];   // [256,256]
    const float* V_w     = (const float*)d_in[4];   // [256,256]
    const float* W_w     = (const float*)d_in[5];   // [256,256]
    const float* prelu_a = (const float*)d_in[6];   // [1]
    float*       out     = (float*)d_out;           // [4096,64,256]

    precompute_A_kernel<<<N_DIM, 256>>>(h_in, w_in, U_w, V_w);
    fused_update_kernel<<<NBLK, 256>>>(s_t, h_in, w_in, W_w, prelu_a, out);
}

// round 4
// speedup vs baseline: 1.0702x; 1.0702x over previous
#include <cuda_runtime.h>

#define B_TOT 4096
#define N_DIM 64
#define H_DIM 256
#define GB    8                 // batch rows per block in epilogue kernel
#define NBLK  (B_TOT / GB)      // 512

#define BM 128
#define BN 64
#define BK 16

// Precomputed tensors (static device globals — no runtime allocation)
__device__ float g_A [N_DIM * H_DIM];      //  64 KB: h@U^T + w@V^T
__device__ float g_Ws[B_TOT * H_DIM];      //   4 MB: s_t @ W_w^T
__device__ float g_G [B_TOT * N_DIM];      //   1 MB: sigmoid(s_t @ (h+w)^T)

// ---------------------------------------------------------------------------
// Kernel A: precompute A[n,k] = sum_h h[n,h]*U_w[k,h] + w[n,h]*V_w[k,h]
// grid = 64 (one per n), 256 threads (one per k)
// ---------------------------------------------------------------------------
__global__ __launch_bounds__(256) void precompute_A_kernel(
    const float* __restrict__ h_in, const float* __restrict__ w_in,
    const float* __restrict__ U_w, const float* __restrict__ V_w)
{
    __shared__ float hrow[H_DIM];
    __shared__ float wrow[H_DIM];
    __shared__ float utile[H_DIM * 20];
    __shared__ float vtile[H_DIM * 20];

    const int n = blockIdx.x;
    const int t = threadIdx.x;

    hrow[t] = h_in[n * H_DIM + t];
    wrow[t] = w_in[n * H_DIM + t];

    const float4* U4  = (const float4*)U_w;
    const float4* V4  = (const float4*)V_w;
    float4*       ut4 = (float4*)utile;
    float4*       vt4 = (float4*)vtile;
    const float4* hr4 = (const float4*)hrow;
    const float4* wr4 = (const float4*)wrow;

    float acc = 0.0f;

    #pragma unroll 1
    for (int c = 0; c < 16; c++) {
        __syncthreads();
        #pragma unroll
        for (int it = 0; it < 4; it++) {
            int idx = it * 256 + t;
            int kk  = idx >> 2;
            int j   = idx & 3;
            ut4[kk * 5 + j] = U4[kk * 64 + c * 4 + j];
            vt4[kk * 5 + j] = V4[kk * 64 + c * 4 + j];
        }
        __syncthreads();
        #pragma unroll
        for (int j = 0; j < 4; j++) {
            float4 u  = ut4[t * 5 + j];
            float4 v  = vt4[t * 5 + j];
            float4 hh = hr4[c * 4 + j];
            float4 ww = wr4[c * 4 + j];
            acc = fmaf(u.x, hh.x, acc); acc = fmaf(u.y, hh.y, acc);
            acc = fmaf(u.z, hh.z, acc); acc = fmaf(u.w, hh.w, acc);
            acc = fmaf(v.x, ww.x, acc); acc = fmaf(v.y, ww.y, acc);
            acc = fmaf(v.z, ww.z, acc); acc = fmaf(v.w, ww.w, acc);
        }
    }
    g_A[n * H_DIM + t] = acc;
}

// ---------------------------------------------------------------------------
// Kernel B: tiled GEMM.  C[m][n] = sum_h s_t[m][h] * Brow[n][h]
//   blockIdx.y < 4 : Brow = W_w rows      -> g_Ws (cols tile_n*64 .. +64)
//   blockIdx.y ==4 : Brow = (h+w) rows    -> g_G  (sigmoid applied)
// 256 threads; thread (ty 0..15, tx 0..15) computes an 8x4 sub-tile.
// ---------------------------------------------------------------------------
__global__ __launch_bounds__(256) void gemm_kernel(
    const float* __restrict__ s_t, const float* __restrict__ W_w,
    const float* __restrict__ h_in, const float* __restrict__ w_in)
{
    __shared__ float sA[BK][BM + 4];   // [k][m]
    __shared__ float sB[BK][BN + 4];   // [k][n]

    const int tile_n  = blockIdx.y;
    const bool is_gate = (tile_n == 4);
    const int m0 = blockIdx.x * BM;
    const int t  = threadIdx.x;
    const int ty = t >> 4;     // 0..15 -> m rows ty*8..+8
    const int tx = t & 15;     // 0..15 -> n cols tx*4..+4

    float acc[8][4];
    #pragma unroll
    for (int i = 0; i < 8; i++)
        #pragma unroll
        for (int j = 0; j < 4; j++) acc[i][j] = 0.0f;

    #pragma unroll 1
    for (int c0 = 0; c0 < H_DIM; c0 += BK) {
        __syncthreads();
        // ---- load A tile: 128 rows x 16 k  (512 float4, 2 per thread) ----
        #pragma unroll
        for (int r = 0; r < 2; r++) {
            int f   = t + r * 256;
            int row = f >> 2;
            int kq  = f & 3;
            float4 v = *(const float4*)&s_t[(m0 + row) * H_DIM + c0 + kq * 4];
            sA[kq * 4 + 0][row] = v.x;
            sA[kq * 4 + 1][row] = v.y;
            sA[kq * 4 + 2][row] = v.z;
            sA[kq * 4 + 3][row] = v.w;
        }
        // ---- load B tile: 64 rows x 16 k (256 float4, 1 per thread) ----
        {
            int row = t >> 2;
            int kq  = t & 3;
            float4 v;
            if (!is_gate) {
                v = *(const float4*)&W_w[(tile_n * 64 + row) * H_DIM + c0 + kq * 4];
            } else {
                float4 a = *(const float4*)&h_in[row * H_DIM + c0 + kq * 4];
                float4 b = *(const float4*)&w_in[row * H_DIM + c0 + kq * 4];
                v = make_float4(a.x + b.x, a.y + b.y, a.z + b.z, a.w + b.w);
            }
            sB[kq * 4 + 0][row] = v.x;
            sB[kq * 4 + 1][row] = v.y;
            sB[kq * 4 + 2][row] = v.z;
            sB[kq * 4 + 3][row] = v.w;
        }
        __syncthreads();

        #pragma unroll
        for (int kk = 0; kk < BK; kk++) {
            float4 a0 = *(const float4*)&sA[kk][ty * 8];
            float4 a1 = *(const float4*)&sA[kk][ty * 8 + 4];
            float4 b  = *(const float4*)&sB[kk][tx * 4];
            float am[8] = {a0.x, a0.y, a0.z, a0.w, a1.x, a1.y, a1.z, a1.w};
            float bn[4] = {b.x, b.y, b.z, b.w};
            #pragma unroll
            for (int i = 0; i < 8; i++)
                #pragma unroll
                for (int j = 0; j < 4; j++)
                    acc[i][j] = fmaf(am[i], bn[j], acc[i][j]);
        }
    }

    // ---- epilogue ----
    if (!is_gate) {
        #pragma unroll
        for (int i = 0; i < 8; i++) {
            int row = m0 + ty * 8 + i;
            float4 v = make_float4(acc[i][0], acc[i][1], acc[i][2], acc[i][3]);
            *(float4*)&g_Ws[row * H_DIM + tile_n * 64 + tx * 4] = v;
        }
    } else {
        #pragma unroll
        for (int i = 0; i < 8; i++) {
            int row = m0 + ty * 8 + i;
            float4 v;
            v.x = 1.0f / (1.0f + __expf(-acc[i][0]));
            v.y = 1.0f / (1.0f + __expf(-acc[i][1]));
            v.z = 1.0f / (1.0f + __expf(-acc[i][2]));
            v.w = 1.0f / (1.0f + __expf(-acc[i][3]));
            *(float4*)&g_G[row * N_DIM + tx * 4] = v;
        }
    }
}

// ---------------------------------------------------------------------------
// Kernel C: pure streaming epilogue — candidate + normalize + store.
// grid = 512 blocks x 8 batch rows; 256 threads = 8 warps; warp owns 8 n's.
// ---------------------------------------------------------------------------
__global__ __launch_bounds__(256) void ew_kernel(
    const float* __restrict__ h_in, const float* __restrict__ prelu_a,
    float* __restrict__ out)
{
    __shared__ float wssm[GB * H_DIM];    // Ws rows   8 KB
    __shared__ float gsm [GB * N_DIM];    // gates     2 KB

    const int t    = threadIdx.x;
    const int lane = t & 31;
    const int wid  = t >> 5;
    const int b0   = blockIdx.x * GB;

    #pragma unroll
    for (int p = 0; p < GB; p++)
        wssm[p * H_DIM + t] = g_Ws[(b0 + p) * H_DIM + t];
    #pragma unroll
    for (int p = 0; p < 2; p++)
        gsm[p * 256 + t] = g_G[b0 * N_DIM + p * 256 + t];
    __syncthreads();

    const float   a0  = prelu_a[0];
    const float4* A4  = (const float4*)g_A;
    const float4* h4  = (const float4*)h_in;
    const float4* ws4 = (const float4*)wssm;
    float4*       o4  = (float4*)out;

    #pragma unroll 1
    for (int i = 0; i < 8; i++) {
        int n = wid * 8 + i;
        float4 Aa = A4[n * 64 + lane];
        float4 Ab = A4[n * 64 + 32 + lane];
        float4 ha = h4[n * 64 + lane];
        float4 hb = h4[n * 64 + 32 + lane];

        #pragma unroll
        for (int g = 0; g < GB; g++) {
            float4 wa = ws4[g * 64 + lane];
            float4 wb = ws4[g * 64 + 32 + lane];
            float  gv = gsm[g * N_DIM + n];

            float v0, v1, v2, v3, v4v, v5, v6, v7;
            float ss = 0.0f;
            #define COMP(vv, Ae, we, he)                                     \
                {                                                            \
                    float x = (Ae) + (we);                                   \
                    float c = fmaxf(x, 0.0f) + a0 * fminf(x, 0.0f);          \
                    vv = fmaf(gv, c, (he));                                  \
                    ss = fmaf(vv, vv, ss);                                   \
                }
            COMP(v0,  Aa.x, wa.x, ha.x)
            COMP(v1,  Aa.y, wa.y, ha.y)
            COMP(v2,  Aa.z, wa.z, ha.z)
            COMP(v3,  Aa.w, wa.w, ha.w)
            COMP(v4v, Ab.x, wb.x, hb.x)
            COMP(v5,  Ab.y, wb.y, hb.y)
            COMP(v6,  Ab.z, wb.z, hb.z)
            COMP(v7,  Ab.w, wb.w, hb.w)
            #undef COMP

            #pragma unroll
            for (int off = 16; off > 0; off >>= 1)
                ss += __shfl_xor_sync(0xffffffffu, ss, off);
            float inv = rsqrtf(ss);

            long base = ((long)(b0 + g) * N_DIM + n) * 64;
            o4[base + lane]      = make_float4(v0 * inv,  v1 * inv, v2 * inv, v3 * inv);
            o4[base + 32 + lane] = make_float4(v4v * inv, v5 * inv, v6 * inv, v7 * inv);
        }
    }
}

// ---------------------------------------------------------------------------
extern "C" void kernel_launch(void* const* d_in, const int* in_sizes, int n_in,
                              void* d_out, int out_size)
{
    const float* s_t     = (const float*)d_in[0];   // [4096,256]
    const float* h_in    = (const float*)d_in[1];   // [1,64,256]
    const float* w_in    = (const float*)d_in[2];   // [1,64,256]
    const float* U_w     = (const float*)d_in[3];   // [256,256]
    const float* V_w     = (const float*)d_in[4];   // [256,256]
    const float* W_w     = (const float*)d_in[5];   // [256,256]
    const float* prelu_a = (const float*)d_in[6];   // [1]
    float*       out     = (float*)d_out;           // [4096,64,256]

    precompute_A_kernel<<<N_DIM, 256>>>(h_in, w_in, U_w, V_w);

    dim3 ggrid(B_TOT / BM, 5);                      // 32 x 5
    gemm_kernel<<<ggrid, 256>>>(s_t, W_w, h_in, w_in);

    ew_kernel<<<NBLK, 256>>>(h_in, prelu_a, out);
}

// round 8
// speedup vs baseline: 1.2142x; 1.1346x over previous
#include <cuda_runtime.h>

#define B_TOT 4096
#define N_DIM 64
#define H_DIM 256
#define GB    8                 // batch rows per block in epilogue kernel
#define NBLK  (B_TOT / GB)      // 512

#define BM 128
#define BN 64
#define BK 16

// Precomputed tensors (static device globals — no runtime allocation)
__device__ float g_A [N_DIM * H_DIM];      //  64 KB: h@U^T + w@V^T
__device__ float g_Ws[B_TOT * H_DIM];      //   4 MB: s_t @ W_w^T
__device__ float g_G [B_TOT * N_DIM];      //   1 MB: sigmoid(s_t @ (h+w)^T)

// ---------------------------------------------------------------------------
// Kernel B: tiled GEMM, three roles selected by blockIdx.y:
//   y in 0..3 : C = s_t @ W_w^T   tile cols y*64..+64        -> g_Ws
//   y == 4    : C = s_t @ (h+w)^T (sigmoid applied)          -> g_G
//   y == 5    : A = h@U^T + w@V^T (concat-K GEMM, 4 blocks)  -> g_A
// 256 threads. Ws/gate: thread = 8x4 sub-tile of a 128x64 tile.
// A plane:     thread = 4x4 sub-tile of the 64x64 tile, K=512 (h|w concat).
// ---------------------------------------------------------------------------
__global__ __launch_bounds__(256) void gemm_kernel(
    const float* __restrict__ s_t, const float* __restrict__ W_w,
    const float* __restrict__ h_in, const float* __restrict__ w_in,
    const float* __restrict__ U_w, const float* __restrict__ V_w)
{
    __shared__ float sA[BK][BM + 4];   // [k][m]
    __shared__ float sB[BK][BN + 4];   // [k][n]

    const int t  = threadIdx.x;
    const int ty = t >> 4;     // 0..15
    const int tx = t & 15;     // 0..15

    // ======================= A plane (y == 5) ==============================
    if (blockIdx.y == 5) {
        if (blockIdx.x >= 4) return;
        const int k0 = blockIdx.x * 64;      // output col tile of A

        float acc[4][4];
        #pragma unroll
        for (int i = 0; i < 4; i++)
            #pragma unroll
            for (int j = 0; j < 4; j++) acc[i][j] = 0.0f;

        #pragma unroll 1
        for (int c0 = 0; c0 < 2 * H_DIM; c0 += BK) {
            const bool second = (c0 >= H_DIM);
            const float* Ap = second ? w_in : h_in;
            const float* Bp = second ? V_w : U_w;
            const int cc = c0 & (H_DIM - 1);

            __syncthreads();
            {   // load 64x16 tiles: one float4 per thread each
                int row = t >> 2;
                int kq  = t & 3;
                float4 va = *(const float4*)&Ap[row * H_DIM + cc + kq * 4];
                sA[kq * 4 + 0][row] = va.x;
                sA[kq * 4 + 1][row] = va.y;
                sA[kq * 4 + 2][row] = va.z;
                sA[kq * 4 + 3][row] = va.w;
                float4 vb = *(const float4*)&Bp[(k0 + row) * H_DIM + cc + kq * 4];
                sB[kq * 4 + 0][row] = vb.x;
                sB[kq * 4 + 1][row] = vb.y;
                sB[kq * 4 + 2][row] = vb.z;
                sB[kq * 4 + 3][row] = vb.w;
            }
            __syncthreads();

            #pragma unroll
            for (int kk = 0; kk < BK; kk++) {
                float4 a = *(const float4*)&sA[kk][ty * 4];
                float4 b = *(const float4*)&sB[kk][tx * 4];
                float am[4] = {a.x, a.y, a.z, a.w};
                float bn[4] = {b.x, b.y, b.z, b.w};
                #pragma unroll
                for (int i = 0; i < 4; i++)
                    #pragma unroll
                    for (int j = 0; j < 4; j++)
                        acc[i][j] = fmaf(am[i], bn[j], acc[i][j]);
            }
        }
        #pragma unroll
        for (int i = 0; i < 4; i++) {
            float4 v = make_float4(acc[i][0], acc[i][1], acc[i][2], acc[i][3]);
            *(float4*)&g_A[(ty * 4 + i) * H_DIM + k0 + tx * 4] = v;
        }
        return;
    }

    // ==================== Ws / gate planes (y 0..4) =========================
    const int tile_n   = blockIdx.y;
    const bool is_gate = (tile_n == 4);
    const int m0 = blockIdx.x * BM;

    float acc[8][4];
    #pragma unroll
    for (int i = 0; i < 8; i++)
        #pragma unroll
        for (int j = 0; j < 4; j++) acc[i][j] = 0.0f;

    #pragma unroll 1
    for (int c0 = 0; c0 < H_DIM; c0 += BK) {
        __syncthreads();
        // ---- load A tile: 128 rows x 16 k (512 float4, 2 per thread) ----
        #pragma unroll
        for (int r = 0; r < 2; r++) {
            int f   = t + r * 256;
            int row = f >> 2;
            int kq  = f & 3;
            float4 v = *(const float4*)&s_t[(m0 + row) * H_DIM + c0 + kq * 4];
            sA[kq * 4 + 0][row] = v.x;
            sA[kq * 4 + 1][row] = v.y;
            sA[kq * 4 + 2][row] = v.z;
            sA[kq * 4 + 3][row] = v.w;
        }
        // ---- load B tile: 64 rows x 16 k (256 float4, 1 per thread) ----
        {
            int row = t >> 2;
            int kq  = t & 3;
            float4 v;
            if (!is_gate) {
                v = *(const float4*)&W_w[(tile_n * 64 + row) * H_DIM + c0 + kq * 4];
            } else {
                float4 a = *(const float4*)&h_in[row * H_DIM + c0 + kq * 4];
                float4 b = *(const float4*)&w_in[row * H_DIM + c0 + kq * 4];
                v = make_float4(a.x + b.x, a.y + b.y, a.z + b.z, a.w + b.w);
            }
            sB[kq * 4 + 0][row] = v.x;
            sB[kq * 4 + 1][row] = v.y;
            sB[kq * 4 + 2][row] = v.z;
            sB[kq * 4 + 3][row] = v.w;
        }
        __syncthreads();

        #pragma unroll
        for (int kk = 0; kk < BK; kk++) {
            float4 a0 = *(const float4*)&sA[kk][ty * 8];
            float4 a1 = *(const float4*)&sA[kk][ty * 8 + 4];
            float4 b  = *(const float4*)&sB[kk][tx * 4];
            float am[8] = {a0.x, a0.y, a0.z, a0.w, a1.x, a1.y, a1.z, a1.w};
            float bn[4] = {b.x, b.y, b.z, b.w};
            #pragma unroll
            for (int i = 0; i < 8; i++)
                #pragma unroll
                for (int j = 0; j < 4; j++)
                    acc[i][j] = fmaf(am[i], bn[j], acc[i][j]);
        }
    }

    if (!is_gate) {
        #pragma unroll
        for (int i = 0; i < 8; i++) {
            int row = m0 + ty * 8 + i;
            float4 v = make_float4(acc[i][0], acc[i][1], acc[i][2], acc[i][3]);
            *(float4*)&g_Ws[row * H_DIM + tile_n * 64 + tx * 4] = v;
        }
    } else {
        #pragma unroll
        for (int i = 0; i < 8; i++) {
            int row = m0 + ty * 8 + i;
            float4 v;
            v.x = 1.0f / (1.0f + __expf(-acc[i][0]));
            v.y = 1.0f / (1.0f + __expf(-acc[i][1]));
            v.z = 1.0f / (1.0f + __expf(-acc[i][2]));
            v.w = 1.0f / (1.0f + __expf(-acc[i][3]));
            *(float4*)&g_G[row * N_DIM + tx * 4] = v;
        }
    }
}

// ---------------------------------------------------------------------------
// Kernel C: pure streaming epilogue — candidate + normalize + store.
// grid = 512 blocks x 8 batch rows; 256 threads = 8 warps; warp owns 8 n's.
// ---------------------------------------------------------------------------
__global__ __launch_bounds__(256) void ew_kernel(
    const float* __restrict__ h_in, const float* __restrict__ prelu_a,
    float* __restrict__ out)
{
    __shared__ float wssm[GB * H_DIM];    // Ws rows   8 KB
    __shared__ float gsm [GB * N_DIM];    // gates     2 KB

    const int t    = threadIdx.x;
    const int lane = t & 31;
    const int wid  = t >> 5;
    const int b0   = blockIdx.x * GB;

    #pragma unroll
    for (int p = 0; p < GB; p++)
        wssm[p * H_DIM + t] = g_Ws[(b0 + p) * H_DIM + t];
    #pragma unroll
    for (int p = 0; p < 2; p++)
        gsm[p * 256 + t] = g_G[b0 * N_DIM + p * 256 + t];
    __syncthreads();

    const float   a0  = prelu_a[0];
    const float4* A4  = (const float4*)g_A;
    const float4* h4  = (const float4*)h_in;
    const float4* ws4 = (const float4*)wssm;
    float4*       o4  = (float4*)out;

    #pragma unroll 1
    for (int i = 0; i < 8; i++) {
        int n = wid * 8 + i;
        float4 Aa = A4[n * 64 + lane];
        float4 Ab = A4[n * 64 + 32 + lane];
        float4 ha = h4[n * 64 + lane];
        float4 hb = h4[n * 64 + 32 + lane];

        #pragma unroll
        for (int g = 0; g < GB; g++) {
            float4 wa = ws4[g * 64 + lane];
            float4 wb = ws4[g * 64 + 32 + lane];
            float  gv = gsm[g * N_DIM + n];

            float v0, v1, v2, v3, v4v, v5, v6, v7;
            float ss = 0.0f;
            #define COMP(vv, Ae, we, he)                                     \
                {                                                            \
                    float x = (Ae) + (we);                                   \
                    float c = fmaxf(x, 0.0f) + a0 * fminf(x, 0.0f);          \
                    vv = fmaf(gv, c, (he));                                  \
                    ss = fmaf(vv, vv, ss);                                   \
                }
            COMP(v0,  Aa.x, wa.x, ha.x)
            COMP(v1,  Aa.y, wa.y, ha.y)
            COMP(v2,  Aa.z, wa.z, ha.z)
            COMP(v3,  Aa.w, wa.w, ha.w)
            COMP(v4v, Ab.x, wb.x, hb.x)
            COMP(v5,  Ab.y, wb.y, hb.y)
            COMP(v6,  Ab.z, wb.z, hb.z)
            COMP(v7,  Ab.w, wb.w, hb.w)
            #undef COMP

            #pragma unroll
            for (int off = 16; off > 0; off >>= 1)
                ss += __shfl_xor_sync(0xffffffffu, ss, off);
            float inv = rsqrtf(ss);

            long base = ((long)(b0 + g) * N_DIM + n) * 64;
            o4[base + lane]      = make_float4(v0 * inv,  v1 * inv, v2 * inv, v3 * inv);
            o4[base + 32 + lane] = make_float4(v4v * inv, v5 * inv, v6 * inv, v7 * inv);
        }
    }
}

// ---------------------------------------------------------------------------
extern "C" void kernel_launch(void* const* d_in, const int* in_sizes, int n_in,
                              void* d_out, int out_size)
{
    const float* s_t     = (const float*)d_in[0];   // [4096,256]
    const float* h_in    = (const float*)d_in[1];   // [1,64,256]
    const float* w_in    = (const float*)d_in[2];   // [1,64,256]
    const float* U_w     = (const float*)d_in[3];   // [256,256]
    const float* V_w     = (const float*)d_in[4];   // [256,256]
    const float* W_w     = (const float*)d_in[5];   // [256,256]
    const float* prelu_a = (const float*)d_in[6];   // [1]
    float*       out     = (float*)d_out;           // [4096,64,256]

    dim3 ggrid(B_TOT / BM, 6);                      // 32 x 6 (y=5: A plane, 4 active)
    gemm_kernel<<<ggrid, 256>>>(s_t, W_w, h_in, w_in, U_w, V_w);

    ew_kernel<<<NBLK, 256>>>(h_in, prelu_a, out);
}

// round 9
// speedup vs baseline: 1.2444x; 1.0249x over previous
#include <cuda_runtime.h>

#define B_TOT 4096
#define N_DIM 64
#define H_DIM 256
#define GB    8                 // batch rows per block in epilogue kernel
#define NBLK  (B_TOT / GB)      // 512

#define BM 64
#define BN 64
#define BK 16

// Precomputed tensors (static device globals — no runtime allocation)
__device__ float g_A [N_DIM * H_DIM];      //  64 KB: h@U^T + w@V^T
__device__ float g_Ws[B_TOT * H_DIM];      //   4 MB: s_t @ W_w^T
__device__ float g_G [B_TOT * N_DIM];      //   1 MB: sigmoid(s_t @ (h+w)^T)

// ---------------------------------------------------------------------------
// Kernel B: tiled GEMM, roles by blockIdx.y:
//   y in 0..3 : C = s_t @ W_w^T   tile cols y*64..+64        -> g_Ws
//   y == 4    : C = s_t @ (h+w)^T (sigmoid applied)          -> g_G
//   y == 5    : A = h@U^T + w@V^T (concat-K GEMM, 4 blocks)  -> g_A
// 256 threads; every thread computes a 4x4 sub-tile of a 64x64 tile.
// grid = (64, 6) = 384 blocks -> ~2.6 waves on 148 SMs.
// ---------------------------------------------------------------------------
__global__ __launch_bounds__(256) void gemm_kernel(
    const float* __restrict__ s_t, const float* __restrict__ W_w,
    const float* __restrict__ h_in, const float* __restrict__ w_in,
    const float* __restrict__ U_w, const float* __restrict__ V_w)
{
    __shared__ float sA[BK][BM + 4];   // [k][m]
    __shared__ float sB[BK][BN + 4];   // [k][n]

    const int t  = threadIdx.x;
    const int ty = t >> 4;     // 0..15
    const int tx = t & 15;     // 0..15

    float acc[4][4];
    #pragma unroll
    for (int i = 0; i < 4; i++)
        #pragma unroll
        for (int j = 0; j < 4; j++) acc[i][j] = 0.0f;

    const int row = t >> 2;    // 0..63 (tile-load row)
    const int kq  = t & 3;     // 0..3  (k quad)

    // ======================= A plane (y == 5) ==============================
    if (blockIdx.y == 5) {
        if (blockIdx.x >= 4) return;
        const int k0 = blockIdx.x * 64;      // output col tile of A

        #pragma unroll 1
        for (int c0 = 0; c0 < 2 * H_DIM; c0 += BK) {
            const bool second = (c0 >= H_DIM);
            const float* Ap = second ? w_in : h_in;
            const float* Bp = second ? V_w : U_w;
            const int cc = c0 & (H_DIM - 1);

            __syncthreads();
            {
                float4 va = *(const float4*)&Ap[row * H_DIM + cc + kq * 4];
                sA[kq * 4 + 0][row] = va.x;
                sA[kq * 4 + 1][row] = va.y;
                sA[kq * 4 + 2][row] = va.z;
                sA[kq * 4 + 3][row] = va.w;
                float4 vb = *(const float4*)&Bp[(k0 + row) * H_DIM + cc + kq * 4];
                sB[kq * 4 + 0][row] = vb.x;
                sB[kq * 4 + 1][row] = vb.y;
                sB[kq * 4 + 2][row] = vb.z;
                sB[kq * 4 + 3][row] = vb.w;
            }
            __syncthreads();

            #pragma unroll
            for (int kk = 0; kk < BK; kk++) {
                float4 a = *(const float4*)&sA[kk][ty * 4];
                float4 b = *(const float4*)&sB[kk][tx * 4];
                float am[4] = {a.x, a.y, a.z, a.w};
                float bn[4] = {b.x, b.y, b.z, b.w};
                #pragma unroll
                for (int i = 0; i < 4; i++)
                    #pragma unroll
                    for (int j = 0; j < 4; j++)
                        acc[i][j] = fmaf(am[i], bn[j], acc[i][j]);
            }
        }
        #pragma unroll
        for (int i = 0; i < 4; i++) {
            float4 v = make_float4(acc[i][0], acc[i][1], acc[i][2], acc[i][3]);
            *(float4*)&g_A[(ty * 4 + i) * H_DIM + k0 + tx * 4] = v;
        }
        return;
    }

    // ==================== Ws / gate planes (y 0..4) =========================
    const int tile_n   = blockIdx.y;
    const bool is_gate = (tile_n == 4);
    const int m0 = blockIdx.x * BM;

    #pragma unroll 1
    for (int c0 = 0; c0 < H_DIM; c0 += BK) {
        __syncthreads();
        {   // ---- A tile: 64 rows x 16 k (one float4 per thread) ----
            float4 v = *(const float4*)&s_t[(m0 + row) * H_DIM + c0 + kq * 4];
            sA[kq * 4 + 0][row] = v.x;
            sA[kq * 4 + 1][row] = v.y;
            sA[kq * 4 + 2][row] = v.z;
            sA[kq * 4 + 3][row] = v.w;
        }
        {   // ---- B tile: 64 rows x 16 k (one float4 per thread) ----
            float4 v;
            if (!is_gate) {
                v = *(const float4*)&W_w[(tile_n * 64 + row) * H_DIM + c0 + kq * 4];
            } else {
                float4 a = *(const float4*)&h_in[row * H_DIM + c0 + kq * 4];
                float4 b = *(const float4*)&w_in[row * H_DIM + c0 + kq * 4];
                v = make_float4(a.x + b.x, a.y + b.y, a.z + b.z, a.w + b.w);
            }
            sB[kq * 4 + 0][row] = v.x;
            sB[kq * 4 + 1][row] = v.y;
            sB[kq * 4 + 2][row] = v.z;
            sB[kq * 4 + 3][row] = v.w;
        }
        __syncthreads();

        #pragma unroll
        for (int kk = 0; kk < BK; kk++) {
            float4 a = *(const float4*)&sA[kk][ty * 4];
            float4 b = *(const float4*)&sB[kk][tx * 4];
            float am[4] = {a.x, a.y, a.z, a.w};
            float bn[4] = {b.x, b.y, b.z, b.w};
            #pragma unroll
            for (int i = 0; i < 4; i++)
                #pragma unroll
                for (int j = 0; j < 4; j++)
                    acc[i][j] = fmaf(am[i], bn[j], acc[i][j]);
        }
    }

    if (!is_gate) {
        #pragma unroll
        for (int i = 0; i < 4; i++) {
            int r = m0 + ty * 4 + i;
            float4 v = make_float4(acc[i][0], acc[i][1], acc[i][2], acc[i][3]);
            *(float4*)&g_Ws[r * H_DIM + tile_n * 64 + tx * 4] = v;
        }
    } else {
        #pragma unroll
        for (int i = 0; i < 4; i++) {
            int r = m0 + ty * 4 + i;
            float4 v;
            v.x = 1.0f / (1.0f + __expf(-acc[i][0]));
            v.y = 1.0f / (1.0f + __expf(-acc[i][1]));
            v.z = 1.0f / (1.0f + __expf(-acc[i][2]));
            v.w = 1.0f / (1.0f + __expf(-acc[i][3]));
            *(float4*)&g_G[r * N_DIM + tx * 4] = v;
        }
    }
}

// ---------------------------------------------------------------------------
// Kernel C: pure streaming epilogue — candidate + normalize + store.
// grid = 512 blocks x 8 batch rows; 256 threads = 8 warps; warp owns 8 n's.
// Reg-capped to 64 (4 blocks/SM -> 50% occupancy) to keep stores flowing.
// ---------------------------------------------------------------------------
__global__ __launch_bounds__(256, 4) void ew_kernel(
    const float* __restrict__ h_in, const float* __restrict__ prelu_a,
    float* __restrict__ out)
{
    __shared__ float wssm[GB * H_DIM];    // Ws rows   8 KB
    __shared__ float gsm [GB * N_DIM];    // gates     2 KB

    const int t    = threadIdx.x;
    const int lane = t & 31;
    const int wid  = t >> 5;
    const int b0   = blockIdx.x * GB;

    #pragma unroll
    for (int p = 0; p < GB; p++)
        wssm[p * H_DIM + t] = g_Ws[(b0 + p) * H_DIM + t];
    #pragma unroll
    for (int p = 0; p < 2; p++)
        gsm[p * 256 + t] = g_G[b0 * N_DIM + p * 256 + t];
    __syncthreads();

    const float   a0  = prelu_a[0];
    const float4* A4  = (const float4*)g_A;
    const float4* h4  = (const float4*)h_in;
    const float4* ws4 = (const float4*)wssm;
    float4*       o4  = (float4*)out;

    #pragma unroll 1
    for (int i = 0; i < 8; i++) {
        int n = wid * 8 + i;
        float4 Aa = A4[n * 64 + lane];
        float4 Ab = A4[n * 64 + 32 + lane];
        float4 ha = h4[n * 64 + lane];
        float4 hb = h4[n * 64 + 32 + lane];

        #pragma unroll
        for (int g = 0; g < GB; g++) {
            float4 wa = ws4[g * 64 + lane];
            float4 wb = ws4[g * 64 + 32 + lane];
            float  gv = gsm[g * N_DIM + n];

            float v0, v1, v2, v3, v4v, v5, v6, v7;
            float ss = 0.0f;
            #define COMP(vv, Ae, we, he)                                     \
                {                                                            \
                    float x = (Ae) + (we);                                   \
                    float c = fmaxf(x, 0.0f) + a0 * fminf(x, 0.0f);          \
                    vv = fmaf(gv, c, (he));                                  \
                    ss = fmaf(vv, vv, ss);                                   \
                }
            COMP(v0,  Aa.x, wa.x, ha.x)
            COMP(v1,  Aa.y, wa.y, ha.y)
            COMP(v2,  Aa.z, wa.z, ha.z)
            COMP(v3,  Aa.w, wa.w, ha.w)
            COMP(v4v, Ab.x, wb.x, hb.x)
            COMP(v5,  Ab.y, wb.y, hb.y)
            COMP(v6,  Ab.z, wb.z, hb.z)
            COMP(v7,  Ab.w, wb.w, hb.w)
            #undef COMP

            #pragma unroll
            for (int off = 16; off > 0; off >>= 1)
                ss += __shfl_xor_sync(0xffffffffu, ss, off);
            float inv = rsqrtf(ss);

            long base = ((long)(b0 + g) * N_DIM + n) * 64;
            o4[base + lane]      = make_float4(v0 * inv,  v1 * inv, v2 * inv, v3 * inv);
            o4[base + 32 + lane] = make_float4(v4v * inv, v5 * inv, v6 * inv, v7 * inv);
        }
    }
}

// ---------------------------------------------------------------------------
extern "C" void kernel_launch(void* const* d_in, const int* in_sizes, int n_in,
                              void* d_out, int out_size)
{
    const float* s_t     = (const float*)d_in[0];   // [4096,256]
    const float* h_in    = (const float*)d_in[1];   // [1,64,256]
    const float* w_in    = (const float*)d_in[2];   // [1,64,256]
    const float* U_w     = (const float*)d_in[3];   // [256,256]
    const float* V_w     = (const float*)d_in[4];   // [256,256]
    const float* W_w     = (const float*)d_in[5];   // [256,256]
    const float* prelu_a = (const float*)d_in[6];   // [1]
    float*       out     = (float*)d_out;           // [4096,64,256]

    dim3 ggrid(B_TOT / BM, 6);                      // 64 x 6 (y=5: A plane, 4 active)
    gemm_kernel<<<ggrid, 256>>>(s_t, W_w, h_in, w_in, U_w, V_w);

    ew_kernel<<<NBLK, 256>>>(h_in, prelu_a, out);
}

// round 13
// speedup vs baseline: 1.4447x; 1.1609x over previous
#include <cuda_runtime.h>

#define B_TOT 4096
#define N_DIM 64
#define H_DIM 256
#define GB    8                 // batch rows per block in epilogue kernel
#define NBLK  (B_TOT / GB)      // 512

#define BM 64
#define BN 64
#define BK 16
#define GTHR 128                // gemm threads per block

// Precomputed tensors (static device globals — no runtime allocation)
__device__ float g_A [N_DIM * H_DIM];      //  64 KB: h@U^T + w@V^T
__device__ float g_Ws[B_TOT * H_DIM];      //   4 MB: s_t @ W_w^T
__device__ float g_G [B_TOT * N_DIM];      //   1 MB: sigmoid(s_t @ (h+w)^T)

// ---------------------------------------------------------------------------
// Kernel B: double-buffered tiled GEMM, roles by blockIdx.y:
//   y in 0..3 : C = s_t @ W_w^T   tile cols y*64..+64        -> g_Ws  (K=256)
//   y == 4    : C = s_t @ (h+w)^T (sigmoid applied)          -> g_G   (K=256)
//   y == 5    : A = h@U^T + w@V^T (concat-K, 4 blocks)       -> g_A   (K=512)
// 128 threads; each computes an 8x4 sub-tile of a 64x64 tile.
// One barrier per K-chunk; next chunk prefetched to regs during compute.
// ---------------------------------------------------------------------------
__global__ __launch_bounds__(GTHR) void gemm_kernel(
    const float* __restrict__ s_t, const float* __restrict__ W_w,
    const float* __restrict__ h_in, const float* __restrict__ w_in,
    const float* __restrict__ U_w, const float* __restrict__ V_w)
{
    __shared__ float sA[2][BK][BM + 4];
    __shared__ float sB[2][BK][BN + 4];

    const int t     = threadIdx.x;
    const int ty    = t >> 4;          // 0..7  -> rows ty*8
    const int tx    = t & 15;          // 0..15 -> cols tx*4
    const int plane = blockIdx.y;
    const bool is_gate = (plane == 4);
    const bool is_A    = (plane == 5);
    if (is_A && blockIdx.x >= 4) return;

    const int m0 = blockIdx.x * BM;    // row tile (planes 0..4)
    const int k0 = blockIdx.x * 64;    // col tile of A (plane 5)
    const int nchunks = is_A ? 32 : 16;

    // chunk loader: thread r-th element of the 64x16 tile (256 float4 / 128 thr)
    auto loadA = [&](int c, int r) -> float4 {
        int f = t + r * GTHR, row = f >> 2, kq = f & 3;
        if (!is_A)
            return *(const float4*)&s_t[(m0 + row) * H_DIM + c * BK + kq * 4];
        const float* Ap = (c < 16) ? h_in : w_in;
        return *(const float4*)&Ap[row * H_DIM + (c & 15) * BK + kq * 4];
    };
    auto loadB = [&](int c, int r) -> float4 {
        int f = t + r * GTHR, row = f >> 2, kq = f & 3;
        if (is_A) {
            const float* Bp = (c < 16) ? U_w : V_w;
            return *(const float4*)&Bp[(k0 + row) * H_DIM + (c & 15) * BK + kq * 4];
        }
        if (!is_gate)
            return *(const float4*)&W_w[(plane * 64 + row) * H_DIM + c * BK + kq * 4];
        float4 a = *(const float4*)&h_in[row * H_DIM + c * BK + kq * 4];
        float4 b = *(const float4*)&w_in[row * H_DIM + c * BK + kq * 4];
        return make_float4(a.x + b.x, a.y + b.y, a.z + b.z, a.w + b.w);
    };
    auto sts_tile = [&](int buf, const float4* va, const float4* vb) {
        #pragma unroll
        for (int r = 0; r < 2; r++) {
            int f = t + r * GTHR, row = f >> 2, kq = f & 3;
            sA[buf][kq * 4 + 0][row] = va[r].x;
            sA[buf][kq * 4 + 1][row] = va[r].y;
            sA[buf][kq * 4 + 2][row] = va[r].z;
            sA[buf][kq * 4 + 3][row] = va[r].w;
            sB[buf][kq * 4 + 0][row] = vb[r].x;
            sB[buf][kq * 4 + 1][row] = vb[r].y;
            sB[buf][kq * 4 + 2][row] = vb[r].z;
            sB[buf][kq * 4 + 3][row] = vb[r].w;
        }
    };

    float acc[8][4];
    #pragma unroll
    for (int i = 0; i < 8; i++)
        #pragma unroll
        for (int j = 0; j < 4; j++) acc[i][j] = 0.0f;

    float4 pa[2], pb[2];
    #pragma unroll
    for (int r = 0; r < 2; r++) { pa[r] = loadA(0, r); pb[r] = loadB(0, r); }
    sts_tile(0, pa, pb);
    __syncthreads();

    #pragma unroll 1
    for (int c = 0; c < nchunks; c++) {
        const int  cur  = c & 1;
        const bool more = (c + 1 < nchunks);

        if (more) {
            #pragma unroll
            for (int r = 0; r < 2; r++) { pa[r] = loadA(c + 1, r); pb[r] = loadB(c + 1, r); }
        }

        #pragma unroll
        for (int kk = 0; kk < BK; kk++) {
            float4 a0 = *(const float4*)&sA[cur][kk][ty * 8];
            float4 a1 = *(const float4*)&sA[cur][kk][ty * 8 + 4];
            float4 b  = *(const float4*)&sB[cur][kk][tx * 4];
            float am[8] = {a0.x, a0.y, a0.z, a0.w, a1.x, a1.y, a1.z, a1.w};
            float bn[4] = {b.x, b.y, b.z, b.w};
            #pragma unroll
            for (int i = 0; i < 8; i++)
                #pragma unroll
                for (int j = 0; j < 4; j++)
                    acc[i][j] = fmaf(am[i], bn[j], acc[i][j]);
        }

        if (more) {
            sts_tile(cur ^ 1, pa, pb);
            __syncthreads();
        }
    }

    // ---- epilogue ----
    if (is_A) {
        #pragma unroll
        for (int i = 0; i < 8; i++) {
            float4 v = make_float4(acc[i][0], acc[i][1], acc[i][2], acc[i][3]);
            *(float4*)&g_A[(ty * 8 + i) * H_DIM + k0 + tx * 4] = v;
        }
    } else if (!is_gate) {
        #pragma unroll
        for (int i = 0; i < 8; i++) {
            int r = m0 + ty * 8 + i;
            float4 v = make_float4(acc[i][0], acc[i][1], acc[i][2], acc[i][3]);
            *(float4*)&g_Ws[r * H_DIM + plane * 64 + tx * 4] = v;
        }
    } else {
        #pragma unroll
        for (int i = 0; i < 8; i++) {
            int r = m0 + ty * 8 + i;
            float4 v;
            v.x = 1.0f / (1.0f + __expf(-acc[i][0]));
            v.y = 1.0f / (1.0f + __expf(-acc[i][1]));
            v.z = 1.0f / (1.0f + __expf(-acc[i][2]));
            v.w = 1.0f / (1.0f + __expf(-acc[i][3]));
            *(float4*)&g_G[r * N_DIM + tx * 4] = v;
        }
    }
}

// ---------------------------------------------------------------------------
// Kernel C: pure streaming epilogue — candidate + normalize + store.
// grid = 512 blocks x 8 batch rows; 256 threads = 8 warps; warp owns 8 n's.
// Reg-capped to 64 (4 blocks/SM -> 50% occupancy) to keep stores flowing.
// ---------------------------------------------------------------------------
__global__ __launch_bounds__(256, 4) void ew_kernel(
    const float* __restrict__ h_in, const float* __restrict__ prelu_a,
    float* __restrict__ out)
{
    __shared__ float wssm[GB * H_DIM];    // Ws rows   8 KB
    __shared__ float gsm [GB * N_DIM];    // gates     2 KB

    const int t    = threadIdx.x;
    const int lane = t & 31;
    const int wid  = t >> 5;
    const int b0   = blockIdx.x * GB;

    #pragma unroll
    for (int p = 0; p < GB; p++)
        wssm[p * H_DIM + t] = g_Ws[(b0 + p) * H_DIM + t];
    #pragma unroll
    for (int p = 0; p < 2; p++)
        gsm[p * 256 + t] = g_G[b0 * N_DIM + p * 256 + t];
    __syncthreads();

    const float   a0  = prelu_a[0];
    const float4* A4  = (const float4*)g_A;
    const float4* h4  = (const float4*)h_in;
    const float4* ws4 = (const float4*)wssm;
    float4*       o4  = (float4*)out;

    #pragma unroll 1
    for (int i = 0; i < 8; i++) {
        int n = wid * 8 + i;
        float4 Aa = A4[n * 64 + lane];
        float4 Ab = A4[n * 64 + 32 + lane];
        float4 ha = h4[n * 64 + lane];
        float4 hb = h4[n * 64 + 32 + lane];

        #pragma unroll
        for (int g = 0; g < GB; g++) {
            float4 wa = ws4[g * 64 + lane];
            float4 wb = ws4[g * 64 + 32 + lane];
            float  gv = gsm[g * N_DIM + n];

            float v0, v1, v2, v3, v4v, v5, v6, v7;
            float ss0 = 0.0f, ss1 = 0.0f;
            #define COMP(vv, sacc, Ae, we, he)                               \
                {                                                            \
                    float x = (Ae) + (we);                                   \
                    float c = fmaxf(x, 0.0f) + a0 * fminf(x, 0.0f);          \
                    vv = fmaf(gv, c, (he));                                  \
                    sacc = fmaf(vv, vv, sacc);                               \
                }
            COMP(v0,  ss0, Aa.x, wa.x, ha.x)
            COMP(v1,  ss1, Aa.y, wa.y, ha.y)
            COMP(v2,  ss0, Aa.z, wa.z, ha.z)
            COMP(v3,  ss1, Aa.w, wa.w, ha.w)
            COMP(v4v, ss0, Ab.x, wb.x, hb.x)
            COMP(v5,  ss1, Ab.y, wb.y, hb.y)
            COMP(v6,  ss0, Ab.z, wb.z, hb.z)
            COMP(v7,  ss1, Ab.w, wb.w, hb.w)
            #undef COMP

            float ss = ss0 + ss1;
            #pragma unroll
            for (int off = 16; off > 0; off >>= 1)
                ss += __shfl_xor_sync(0xffffffffu, ss, off);
            float inv = rsqrtf(ss);

            long base = ((long)(b0 + g) * N_DIM + n) * 64;
            o4[base + lane]      = make_float4(v0 * inv,  v1 * inv, v2 * inv, v3 * inv);
            o4[base + 32 + lane] = make_float4(v4v * inv, v5 * inv, v6 * inv, v7 * inv);
        }
    }
}

// ---------------------------------------------------------------------------
extern "C" void kernel_launch(void* const* d_in, const int* in_sizes, int n_in,
                              void* d_out, int out_size)
{
    const float* s_t     = (const float*)d_in[0];   // [4096,256]
    const float* h_in    = (const float*)d_in[1];   // [1,64,256]
    const float* w_in    = (const float*)d_in[2];   // [1,64,256]
    const float* U_w     = (const float*)d_in[3];   // [256,256]
    const float* V_w     = (const float*)d_in[4];   // [256,256]
    const float* W_w     = (const float*)d_in[5];   // [256,256]
    const float* prelu_a = (const float*)d_in[6];   // [1]
    float*       out     = (float*)d_out;           // [4096,64,256]

    dim3 ggrid(B_TOT / BM, 6);                      // 64 x 6 (y=5: A plane, 4 active)
    gemm_kernel<<<ggrid, GTHR>>>(s_t, W_w, h_in, w_in, U_w, V_w);

    ew_kernel<<<NBLK, 256>>>(h_in, prelu_a, out);
}